// round 4
// baseline (speedup 1.0000x reference)
#include <cuda_runtime.h>

// Problem-fixed sizes: 100k nodes, 1.25M edges, feats 64 -> 64 -> 32
#define NV_MAX 100000
#define NE_MAX 1250000

// Scratch (module-load allocated; no runtime allocation)
__device__ int   g_cnt[NV_MAX];        // per-dst edge counts / fill cursors
__device__ int   g_row[NV_MAX + 1];    // CSR row pointers (by dst)
__device__ int   g_adj[NE_MAX];        // CSR adjacency: src node per slot
__device__ float g_hn [NV_MAX * 64];   // scaled neighbor mean (reused both layers)
__device__ float g_h1 [NV_MAX * 64];   // layer-1 activations
__device__ int   g_is64;               // 1 if index buffers are int64-layout

// ---------------------------------------------------------------------------
// Detect index dtype: for little-endian int64 with values < 2^31, every odd
// 32-bit word is zero. For random int32 node ids, essentially never.
// ---------------------------------------------------------------------------
__global__ void detect_kernel(const int* __restrict__ idx) {
    int allz = 1;
    #pragma unroll
    for (int i = 1; i < 64; i += 2)
        if (idx[i] != 0) allz = 0;
    g_is64 = allz;
}

// Flag-dispatched index load, clamped into [0, nV)
__device__ __forceinline__ int load_idx(const void* p, int e, int nV) {
    int v = g_is64 ? (int)((const long long*)p)[e] : ((const int*)p)[e];
    return min(max(v, 0), nV - 1);
}

// ---------------------------------------------------------------------------
// Zero the integer counters
// ---------------------------------------------------------------------------
__global__ void zero_counts(int nV) {
    int i = blockIdx.x * blockDim.x + threadIdx.x;
    if (i < nV) g_cnt[i] = 0;
}

// ---------------------------------------------------------------------------
// Histogram of destination degrees
// ---------------------------------------------------------------------------
__global__ void hist_kernel(const void* __restrict__ dst, int nE, int nV) {
    int e = blockIdx.x * blockDim.x + threadIdx.x;
    if (e < nE) atomicAdd(&g_cnt[load_idx(dst, e, nV)], 1);
}

// ---------------------------------------------------------------------------
// Exclusive scan of g_cnt -> g_row. Single block, 1024 threads, chunked
// Hillis-Steele with running carry. Resets g_cnt for reuse as fill cursor.
// ---------------------------------------------------------------------------
__global__ void scan_kernel(int nV) {
    __shared__ int s[1024];
    __shared__ int carry;
    if (threadIdx.x == 0) carry = 0;
    __syncthreads();

    for (int base = 0; base < nV; base += 1024) {
        int i = base + threadIdx.x;
        int v = (i < nV) ? g_cnt[i] : 0;
        s[threadIdx.x] = v;
        __syncthreads();
        #pragma unroll
        for (int off = 1; off < 1024; off <<= 1) {
            int t = (threadIdx.x >= off) ? s[threadIdx.x - off] : 0;
            __syncthreads();
            s[threadIdx.x] += t;
            __syncthreads();
        }
        if (i < nV) {
            g_row[i] = carry + s[threadIdx.x] - v;   // exclusive
            g_cnt[i] = 0;                            // reset cursor
        }
        int tot = s[1023];
        __syncthreads();
        if (threadIdx.x == 0) carry += tot;
        __syncthreads();
    }
    if (threadIdx.x == 0) g_row[nV] = carry;
}

// ---------------------------------------------------------------------------
// Fill CSR adjacency: slot = row[dst] + cursor++, value = src
// ---------------------------------------------------------------------------
__global__ void fill_kernel(const void* __restrict__ src,
                            const void* __restrict__ dst, int nE, int nV) {
    int e = blockIdx.x * blockDim.x + threadIdx.x;
    if (e >= nE) return;
    int d = load_idx(dst, e, nV);
    int p = g_row[d] + atomicAdd(&g_cnt[d], 1);
    if (p < NE_MAX) g_adj[p] = load_idx(src, e, nV);
}

// ---------------------------------------------------------------------------
// Gather aggregation: one warp per node, each lane owns a float2 of the
// 64-float row. Sum over in-neighbors, scale by 1/deg, write g_hn.
// ---------------------------------------------------------------------------
template <int LAYER>
__global__ void agg_kernel(const float* __restrict__ xin, int nV) {
    int warp = (blockIdx.x * blockDim.x + threadIdx.x) >> 5;
    int lane = threadIdx.x & 31;
    if (warp >= nV) return;

    int beg = g_row[warp];
    int end = g_row[warp + 1];

    const float2* f2 = (LAYER == 1) ? reinterpret_cast<const float2*>(xin)
                                    : reinterpret_cast<const float2*>(g_h1);
    float ax = 0.f, ay = 0.f;
    for (int j = beg; j < end; ++j) {
        int s = g_adj[j];
        float2 v = __ldg(f2 + (size_t)s * 32 + lane);
        ax += v.x; ay += v.y;
    }
    float inv = (end > beg) ? (1.0f / (float)(end - beg)) : 0.0f;
    reinterpret_cast<float2*>(g_hn)[(size_t)warp * 32 + lane] =
        make_float2(ax * inv, ay * inv);
}

// ---------------------------------------------------------------------------
// Node kernel, layer 1: h1 = relu( x @ Ws1 + g_hn @ Wn1 + b1 )
// 256 threads = 4 nodes x 64 output channels; 64 nodes per block.
// ---------------------------------------------------------------------------
__global__ void node1_kernel(const float* __restrict__ x,
                             const float* __restrict__ Ws,
                             const float* __restrict__ Wn,
                             const float* __restrict__ b,
                             int nV) {
    __shared__ float sW[128 * 64];   // rows 0..63 = Ws, 64..127 = Wn
    __shared__ float sB[64];
    __shared__ float sIn[4][128];

    for (int i = threadIdx.x; i < 64 * 64; i += 256) {
        sW[i]           = Ws[i];
        sW[64 * 64 + i] = Wn[i];
    }
    if (threadIdx.x < 64) sB[threadIdx.x] = b[threadIdx.x];
    __syncthreads();

    int o = threadIdx.x & 63;
    int y = threadIdx.x >> 6;
    int base = blockIdx.x * 64;

    #pragma unroll 1
    for (int r = 0; r < 16; ++r) {
        int node = base + r * 4 + y;
        if (node < nV) {
            sIn[y][o]      = x   [(size_t)node * 64 + o];
            sIn[y][64 + o] = g_hn[(size_t)node * 64 + o];
        }
        __syncthreads();
        if (node < nV) {
            float acc = sB[o];
            #pragma unroll
            for (int k = 0; k < 128; ++k)
                acc = fmaf(sIn[y][k], sW[k * 64 + o], acc);
            g_h1[(size_t)node * 64 + o] = fmaxf(acc, 0.0f);
        }
        __syncthreads();
    }
}

// ---------------------------------------------------------------------------
// Node kernel, layer 2: out = h1 @ Ws2 + g_hn @ Wn2 + b2  (32 outputs)
// 256 threads = 8 nodes x 32 output channels; 64 nodes per block.
// ---------------------------------------------------------------------------
__global__ void node2_kernel(const float* __restrict__ Ws,
                             const float* __restrict__ Wn,
                             const float* __restrict__ b,
                             float* __restrict__ out,
                             int nV) {
    __shared__ float sW[128 * 32];   // rows 0..63 = Ws2, 64..127 = Wn2
    __shared__ float sB[32];
    __shared__ float sIn[8][128];

    for (int i = threadIdx.x; i < 64 * 32; i += 256) {
        sW[i]           = Ws[i];
        sW[64 * 32 + i] = Wn[i];
    }
    if (threadIdx.x < 32) sB[threadIdx.x] = b[threadIdx.x];
    __syncthreads();

    int o = threadIdx.x & 31;
    int y = threadIdx.x >> 5;
    int base = blockIdx.x * 64;

    #pragma unroll 1
    for (int r = 0; r < 8; ++r) {
        int node = base + r * 8 + y;
        if (node < nV) {
            sIn[y][o]       = g_h1[(size_t)node * 64 + o];
            sIn[y][o + 32]  = g_h1[(size_t)node * 64 + o + 32];
            sIn[y][o + 64]  = g_hn[(size_t)node * 64 + o];
            sIn[y][o + 96]  = g_hn[(size_t)node * 64 + o + 32];
        }
        __syncthreads();
        if (node < nV) {
            float acc = sB[o];
            #pragma unroll
            for (int k = 0; k < 128; ++k)
                acc = fmaf(sIn[y][k], sW[k * 32 + o], acc);
            out[(size_t)node * 32 + o] = acc;
        }
        __syncthreads();
    }
}

// ---------------------------------------------------------------------------
// Launch (kernel launches only — fully graph-capturable)
// ---------------------------------------------------------------------------
extern "C" void kernel_launch(void* const* d_in, const int* in_sizes, int n_in,
                              void* d_out, int out_size) {
    const float* x    = (const float*)d_in[0];
    const void*  src  = d_in[1];
    const void*  dst  = d_in[2];
    const float* Ws1  = (const float*)d_in[3];
    const float* Wn1  = (const float*)d_in[4];
    const float* b1   = (const float*)d_in[5];
    const float* Ws2  = (const float*)d_in[6];
    const float* Wn2  = (const float*)d_in[7];
    const float* b2   = (const float*)d_in[8];
    float*       out  = (float*)d_out;

    int nV = in_sizes[0] / 64;
    int nE = in_sizes[1];

    int eb = (nE + 255) / 256;
    int vb = (nV + 255) / 256;

    detect_kernel<<<1, 1>>>((const int*)dst);
    zero_counts<<<vb, 256>>>(nV);
    hist_kernel<<<eb, 256>>>(dst, nE, nV);
    scan_kernel<<<1, 1024>>>(nV);
    fill_kernel<<<eb, 256>>>(src, dst, nE, nV);

    int ab = (nV * 32 + 255) / 256;       // one warp per node
    int nb = (nV + 63) / 64;

    agg_kernel<1><<<ab, 256>>>(x, nV);
    node1_kernel<<<nb, 256>>>(x, Ws1, Wn1, b1, nV);
    agg_kernel<2><<<ab, 256>>>(nullptr, nV);
    node2_kernel<<<nb, 256>>>(Ws2, Wn2, b2, out, nV);
}

// round 8
// speedup vs baseline: 1.6605x; 1.6605x over previous
#include <cuda_runtime.h>

// Problem-fixed sizes: 100k nodes, 1.25M edges, feats 64 -> 64 -> 32
#define NV_MAX 100000
#define NE_MAX 1250000

// Scratch (module-load allocated; no runtime allocation)
__device__ int   g_cnt[NV_MAX];        // per-dst edge counts / fill cursors
__device__ int   g_row[NV_MAX + 1];    // CSR row pointers (by dst)
__device__ int   g_part[128];          // per-block scan partials
__device__ int   g_adj[NE_MAX];        // CSR adjacency: src node per slot
__device__ float g_hn [NV_MAX * 64];   // scaled neighbor mean (reused both layers)
__device__ float g_h1 [NV_MAX * 64];   // layer-1 activations
__device__ int   g_is64;               // 1 if index buffers are int64-layout

// ---------------------------------------------------------------------------
// Detect index dtype: for little-endian int64 with values < 2^31, every odd
// 32-bit word is zero. For random int32 node ids, essentially never.
// ---------------------------------------------------------------------------
__global__ void detect_kernel(const int* __restrict__ idx) {
    int allz = 1;
    #pragma unroll
    for (int i = 1; i < 64; i += 2)
        if (idx[i] != 0) allz = 0;
    g_is64 = allz;
}

// Flag-dispatched index load, clamped into [0, nV)
__device__ __forceinline__ int load_idx(const void* p, int e, int nV) {
    int v = g_is64 ? (int)((const long long*)p)[e] : ((const int*)p)[e];
    return min(max(v, 0), nV - 1);
}

// ---------------------------------------------------------------------------
// Zero the integer counters
// ---------------------------------------------------------------------------
__global__ void zero_counts(int nV) {
    int i = blockIdx.x * blockDim.x + threadIdx.x;
    if (i < nV) g_cnt[i] = 0;
}

// ---------------------------------------------------------------------------
// Histogram of destination degrees
// ---------------------------------------------------------------------------
__global__ void hist_kernel(const void* __restrict__ dst, int nE, int nV) {
    int e = blockIdx.x * blockDim.x + threadIdx.x;
    if (e < nE) atomicAdd(&g_cnt[load_idx(dst, e, nV)], 1);
}

// ---------------------------------------------------------------------------
// Two-level scan, phase 1: per-block exclusive scan (1024 elems/block) via
// warp shuffles; writes local exclusive prefixes to g_row and the block
// total to g_part[blockIdx.x].
// ---------------------------------------------------------------------------
__global__ void scan_block(int nV) {
    __shared__ int wsum[32];
    int gid  = blockIdx.x * 1024 + threadIdx.x;
    int lane = threadIdx.x & 31;
    int w    = threadIdx.x >> 5;

    int v = (gid < nV) ? g_cnt[gid] : 0;
    int s = v;
    #pragma unroll
    for (int o = 1; o < 32; o <<= 1) {
        int t = __shfl_up_sync(0xFFFFFFFFu, s, o);
        if (lane >= o) s += t;
    }
    if (lane == 31) wsum[w] = s;
    __syncthreads();
    if (w == 0) {
        int t = wsum[lane];
        int ss = t;
        #pragma unroll
        for (int o = 1; o < 32; o <<= 1) {
            int u = __shfl_up_sync(0xFFFFFFFFu, ss, o);
            if (lane >= o) ss += u;
        }
        wsum[lane] = ss - t;   // exclusive warp offsets
    }
    __syncthreads();
    int incl = s + wsum[w];
    if (gid < nV) g_row[gid] = incl - v;          // local exclusive
    if (threadIdx.x == 1023) g_part[blockIdx.x] = incl;  // block total
}

// ---------------------------------------------------------------------------
// Phase 2: single tiny block scans the <=128 block totals (exclusive),
// stores total edge count at g_row[nV].
// ---------------------------------------------------------------------------
__global__ void scan_part(int nb, int nV) {
    __shared__ int wsum[4];
    int lane = threadIdx.x & 31;
    int w    = threadIdx.x >> 5;

    int v = (threadIdx.x < nb) ? g_part[threadIdx.x] : 0;
    int s = v;
    #pragma unroll
    for (int o = 1; o < 32; o <<= 1) {
        int t = __shfl_up_sync(0xFFFFFFFFu, s, o);
        if (lane >= o) s += t;
    }
    if (lane == 31) wsum[w] = s;
    __syncthreads();
    int off = 0;
    for (int i = 0; i < w; ++i) off += wsum[i];
    int incl = s + off;
    if (threadIdx.x < nb) g_part[threadIdx.x] = incl - v;  // exclusive
    if (threadIdx.x == nb - 1) g_row[nV] = incl;
}

// ---------------------------------------------------------------------------
// Phase 3: add block offsets, reset cursors.
// ---------------------------------------------------------------------------
__global__ void scan_add(int nV) {
    int gid = blockIdx.x * 1024 + threadIdx.x;
    if (gid < nV) {
        g_row[gid] += g_part[blockIdx.x];
        g_cnt[gid] = 0;
    }
}

// ---------------------------------------------------------------------------
// Fill CSR adjacency: slot = row[dst] + cursor++, value = src
// ---------------------------------------------------------------------------
__global__ void fill_kernel(const void* __restrict__ src,
                            const void* __restrict__ dst, int nE, int nV) {
    int e = blockIdx.x * blockDim.x + threadIdx.x;
    if (e >= nE) return;
    int d = load_idx(dst, e, nV);
    int p = g_row[d] + atomicAdd(&g_cnt[d], 1);
    if (p < NE_MAX) g_adj[p] = load_idx(src, e, nV);
}

// ---------------------------------------------------------------------------
// Gather aggregation: one warp per node. Each half-warp owns one edge per
// iteration; its 16 lanes read the 64-float row as 16 x float4 (LDG.128).
// Two edges in flight per trip; halves combined with one shfl_xor(16).
// ---------------------------------------------------------------------------
template <int LAYER>
__global__ void agg_kernel(const float* __restrict__ xin, int nV) {
    int warp = (blockIdx.x * blockDim.x + threadIdx.x) >> 5;
    int lane = threadIdx.x & 31;
    if (warp >= nV) return;

    int beg = g_row[warp];
    int end = g_row[warp + 1];

    const float4* f4 = (LAYER == 1) ? reinterpret_cast<const float4*>(xin)
                                    : reinterpret_cast<const float4*>(g_h1);
    int half = lane >> 4;      // 0 or 1: even/odd edges
    int c    = lane & 15;      // float4 chunk within the 64-float row

    float ax = 0.f, ay = 0.f, az = 0.f, aw = 0.f;
    for (int j = beg + half; j < end; j += 2) {
        int s = g_adj[j];
        float4 v = __ldg(f4 + (size_t)s * 16 + c);
        ax += v.x; ay += v.y; az += v.z; aw += v.w;
    }
    // combine even/odd partial sums (lane L <-> lane L^16 hold same chunk)
    ax += __shfl_xor_sync(0xFFFFFFFFu, ax, 16);
    ay += __shfl_xor_sync(0xFFFFFFFFu, ay, 16);
    az += __shfl_xor_sync(0xFFFFFFFFu, az, 16);
    aw += __shfl_xor_sync(0xFFFFFFFFu, aw, 16);

    if (half == 0) {
        float inv = (end > beg) ? (1.0f / (float)(end - beg)) : 0.0f;
        reinterpret_cast<float4*>(g_hn)[(size_t)warp * 16 + c] =
            make_float4(ax * inv, ay * inv, az * inv, aw * inv);
    }
}

// ---------------------------------------------------------------------------
// Node kernel, layer 1: h1 = relu( x @ Ws1 + g_hn @ Wn1 + b1 )
// 256 threads = 64 output channels x 4 y-slots; each thread computes TWO
// nodes per round (reusing each sW LDS for 2 FMAs -> FFMA-bound, not
// LDS-bound). 8 nodes in flight per round, 64 nodes per block.
// ---------------------------------------------------------------------------
__global__ void node1_kernel(const float* __restrict__ x,
                             const float* __restrict__ Ws,
                             const float* __restrict__ Wn,
                             const float* __restrict__ b,
                             int nV) {
    __shared__ float sW[128 * 64];   // rows 0..63 = Ws, 64..127 = Wn
    __shared__ float sB[64];
    __shared__ float sIn[8][128];

    for (int i = threadIdx.x; i < 64 * 64; i += 256) {
        sW[i]           = Ws[i];
        sW[64 * 64 + i] = Wn[i];
    }
    if (threadIdx.x < 64) sB[threadIdx.x] = b[threadIdx.x];
    __syncthreads();

    int o = threadIdx.x & 63;
    int y = threadIdx.x >> 6;       // 0..3
    int base = blockIdx.x * 64;

    #pragma unroll 1
    for (int r = 0; r < 8; ++r) {   // 8 rounds x 8 nodes
        int n0 = base + r * 8 + y;
        int n1 = n0 + 4;
        if (n0 < nV) {
            sIn[y][o]          = x   [(size_t)n0 * 64 + o];
            sIn[y][64 + o]     = g_hn[(size_t)n0 * 64 + o];
        }
        if (n1 < nV) {
            sIn[y + 4][o]      = x   [(size_t)n1 * 64 + o];
            sIn[y + 4][64 + o] = g_hn[(size_t)n1 * 64 + o];
        }
        __syncthreads();
        float acc0 = sB[o], acc1 = acc0;
        #pragma unroll
        for (int k = 0; k < 128; ++k) {
            float w = sW[k * 64 + o];
            acc0 = fmaf(sIn[y][k],     w, acc0);
            acc1 = fmaf(sIn[y + 4][k], w, acc1);
        }
        if (n0 < nV) g_h1[(size_t)n0 * 64 + o] = fmaxf(acc0, 0.0f);
        if (n1 < nV) g_h1[(size_t)n1 * 64 + o] = fmaxf(acc1, 0.0f);
        __syncthreads();
    }
}

// ---------------------------------------------------------------------------
// Node kernel, layer 2: out = h1 @ Ws2 + g_hn @ Wn2 + b2  (32 outputs)
// 256 threads = 32 output channels x 8 y-slots; two nodes per thread,
// 16 nodes in flight, 64 nodes per block.
// ---------------------------------------------------------------------------
__global__ void node2_kernel(const float* __restrict__ Ws,
                             const float* __restrict__ Wn,
                             const float* __restrict__ b,
                             float* __restrict__ out,
                             int nV) {
    __shared__ float sW[128 * 32];   // rows 0..63 = Ws2, 64..127 = Wn2
    __shared__ float sB[32];
    __shared__ float sIn[16][128];

    for (int i = threadIdx.x; i < 64 * 32; i += 256) {
        sW[i]           = Ws[i];
        sW[64 * 32 + i] = Wn[i];
    }
    if (threadIdx.x < 32) sB[threadIdx.x] = b[threadIdx.x];
    __syncthreads();

    int o = threadIdx.x & 31;
    int y = threadIdx.x >> 5;       // 0..7
    int base = blockIdx.x * 64;

    #pragma unroll 1
    for (int r = 0; r < 4; ++r) {   // 4 rounds x 16 nodes
        int n0 = base + r * 16 + y;
        int n1 = n0 + 8;
        if (n0 < nV) {
            sIn[y][o]           = g_h1[(size_t)n0 * 64 + o];
            sIn[y][o + 32]      = g_h1[(size_t)n0 * 64 + o + 32];
            sIn[y][o + 64]      = g_hn[(size_t)n0 * 64 + o];
            sIn[y][o + 96]      = g_hn[(size_t)n0 * 64 + o + 32];
        }
        if (n1 < nV) {
            sIn[y + 8][o]       = g_h1[(size_t)n1 * 64 + o];
            sIn[y + 8][o + 32]  = g_h1[(size_t)n1 * 64 + o + 32];
            sIn[y + 8][o + 64]  = g_hn[(size_t)n1 * 64 + o];
            sIn[y + 8][o + 96]  = g_hn[(size_t)n1 * 64 + o + 32];
        }
        __syncthreads();
        float acc0 = sB[o], acc1 = acc0;
        #pragma unroll
        for (int k = 0; k < 128; ++k) {
            float w = sW[k * 32 + o];
            acc0 = fmaf(sIn[y][k],     w, acc0);
            acc1 = fmaf(sIn[y + 8][k], w, acc1);
        }
        if (n0 < nV) out[(size_t)n0 * 32 + o] = acc0;
        if (n1 < nV) out[(size_t)n1 * 32 + o] = acc1;
        __syncthreads();
    }
}

// ---------------------------------------------------------------------------
// Launch (kernel launches only — fully graph-capturable)
// ---------------------------------------------------------------------------
extern "C" void kernel_launch(void* const* d_in, const int* in_sizes, int n_in,
                              void* d_out, int out_size) {
    const float* x    = (const float*)d_in[0];
    const void*  src  = d_in[1];
    const void*  dst  = d_in[2];
    const float* Ws1  = (const float*)d_in[3];
    const float* Wn1  = (const float*)d_in[4];
    const float* b1   = (const float*)d_in[5];
    const float* Ws2  = (const float*)d_in[6];
    const float* Wn2  = (const float*)d_in[7];
    const float* b2   = (const float*)d_in[8];
    float*       out  = (float*)d_out;

    int nV = in_sizes[0] / 64;
    int nE = in_sizes[1];

    int eb = (nE + 255) / 256;
    int vb = (nV + 255) / 256;
    int sb = (nV + 1023) / 1024;     // scan blocks (98 for 100k), must be <=128

    detect_kernel<<<1, 1>>>((const int*)dst);
    zero_counts<<<vb, 256>>>(nV);
    hist_kernel<<<eb, 256>>>(dst, nE, nV);
    scan_block<<<sb, 1024>>>(nV);
    scan_part<<<1, 128>>>(sb, nV);
    scan_add<<<sb, 1024>>>(nV);
    fill_kernel<<<eb, 256>>>(src, dst, nE, nV);

    int ab = (nV * 32 + 255) / 256;  // one warp per node
    int nb = (nV + 63) / 64;

    agg_kernel<1><<<ab, 256>>>(x, nV);
    node1_kernel<<<nb, 256>>>(x, Ws1, Wn1, b1, nV);
    agg_kernel<2><<<ab, 256>>>(nullptr, nV);
    node2_kernel<<<nb, 256>>>(Ws2, Wn2, b2, out, nV);
}

// round 10
// speedup vs baseline: 1.7933x; 1.0800x over previous
#include <cuda_runtime.h>

// Problem-fixed sizes: 100k nodes, 1.25M edges, feats 64 -> 64 -> 32
#define NV_MAX 100000
#define NE_MAX 1250000

// Scratch (module-load allocated; no runtime allocation)
__device__ int   g_cnt[NV_MAX];        // per-dst edge counts / fill cursors
__device__ int   g_row[NV_MAX + 1];    // CSR row pointers (by dst)
__device__ int   g_part[128];          // per-block scan partials
__device__ int   g_adj[NE_MAX];        // CSR adjacency: src node per slot
__device__ float g_hn [NV_MAX * 64];   // layer-1 neighbor mean (64-dim)
__device__ float g_h1 [NV_MAX * 64];   // layer-1 activations
__device__ float g_z  [NV_MAX * 32];   // z = h1 @ Wn2 (pre-transformed, 32-dim)
__device__ float g_hn2[NV_MAX * 32];   // layer-2 neighbor mean of z (32-dim)
__device__ int   g_is64;               // 1 if index buffers are int64-layout

// ---------------------------------------------------------------------------
// Detect index dtype: little-endian int64 with values < 2^31 has all odd
// 32-bit words zero; random int32 node ids essentially never do.
// ---------------------------------------------------------------------------
__global__ void detect_kernel(const int* __restrict__ idx) {
    int allz = 1;
    #pragma unroll
    for (int i = 1; i < 64; i += 2)
        if (idx[i] != 0) allz = 0;
    g_is64 = allz;
}

__device__ __forceinline__ int load_idx(const void* p, int e, int nV) {
    int v = g_is64 ? (int)((const long long*)p)[e] : ((const int*)p)[e];
    return min(max(v, 0), nV - 1);
}

__global__ void zero_counts(int nV) {
    int i = blockIdx.x * blockDim.x + threadIdx.x;
    if (i < nV) g_cnt[i] = 0;
}

__global__ void hist_kernel(const void* __restrict__ dst, int nE, int nV) {
    int e = blockIdx.x * blockDim.x + threadIdx.x;
    if (e < nE) atomicAdd(&g_cnt[load_idx(dst, e, nV)], 1);
}

// ---------------------------------------------------------------------------
// Two-level exclusive scan of g_cnt -> g_row (phase1/phase2/phase3)
// ---------------------------------------------------------------------------
__global__ void scan_block(int nV) {
    __shared__ int wsum[32];
    int gid  = blockIdx.x * 1024 + threadIdx.x;
    int lane = threadIdx.x & 31;
    int w    = threadIdx.x >> 5;

    int v = (gid < nV) ? g_cnt[gid] : 0;
    int s = v;
    #pragma unroll
    for (int o = 1; o < 32; o <<= 1) {
        int t = __shfl_up_sync(0xFFFFFFFFu, s, o);
        if (lane >= o) s += t;
    }
    if (lane == 31) wsum[w] = s;
    __syncthreads();
    if (w == 0) {
        int t = wsum[lane];
        int ss = t;
        #pragma unroll
        for (int o = 1; o < 32; o <<= 1) {
            int u = __shfl_up_sync(0xFFFFFFFFu, ss, o);
            if (lane >= o) ss += u;
        }
        wsum[lane] = ss - t;
    }
    __syncthreads();
    int incl = s + wsum[w];
    if (gid < nV) g_row[gid] = incl - v;
    if (threadIdx.x == 1023) g_part[blockIdx.x] = incl;
}

__global__ void scan_part(int nb, int nV) {
    __shared__ int wsum[4];
    int lane = threadIdx.x & 31;
    int w    = threadIdx.x >> 5;

    int v = (threadIdx.x < nb) ? g_part[threadIdx.x] : 0;
    int s = v;
    #pragma unroll
    for (int o = 1; o < 32; o <<= 1) {
        int t = __shfl_up_sync(0xFFFFFFFFu, s, o);
        if (lane >= o) s += t;
    }
    if (lane == 31) wsum[w] = s;
    __syncthreads();
    int off = 0;
    for (int i = 0; i < w; ++i) off += wsum[i];
    int incl = s + off;
    if (threadIdx.x < nb) g_part[threadIdx.x] = incl - v;
    if (threadIdx.x == nb - 1) g_row[nV] = incl;
}

__global__ void scan_add(int nV) {
    int gid = blockIdx.x * 1024 + threadIdx.x;
    if (gid < nV) {
        g_row[gid] += g_part[blockIdx.x];
        g_cnt[gid] = 0;
    }
}

__global__ void fill_kernel(const void* __restrict__ src,
                            const void* __restrict__ dst, int nE, int nV) {
    int e = blockIdx.x * blockDim.x + threadIdx.x;
    if (e >= nE) return;
    int d = load_idx(dst, e, nV);
    int p = g_row[d] + atomicAdd(&g_cnt[d], 1);
    if (p < NE_MAX) g_adj[p] = load_idx(src, e, nV);
}

// ---------------------------------------------------------------------------
// Layer-1 aggregation: one warp per node, half-warp per edge (16 x float4
// per 64-float row), two edges in flight, shfl_xor(16) combine.
// ---------------------------------------------------------------------------
__global__ void agg64_kernel(const float* __restrict__ xin, int nV) {
    int warp = (blockIdx.x * blockDim.x + threadIdx.x) >> 5;
    int lane = threadIdx.x & 31;
    if (warp >= nV) return;

    int beg = g_row[warp];
    int end = g_row[warp + 1];

    const float4* f4 = reinterpret_cast<const float4*>(xin);
    int half = lane >> 4;
    int c    = lane & 15;

    float ax = 0.f, ay = 0.f, az = 0.f, aw = 0.f;
    for (int j = beg + half; j < end; j += 2) {
        int s = g_adj[j];
        float4 v = __ldg(f4 + (size_t)s * 16 + c);
        ax += v.x; ay += v.y; az += v.z; aw += v.w;
    }
    ax += __shfl_xor_sync(0xFFFFFFFFu, ax, 16);
    ay += __shfl_xor_sync(0xFFFFFFFFu, ay, 16);
    az += __shfl_xor_sync(0xFFFFFFFFu, az, 16);
    aw += __shfl_xor_sync(0xFFFFFFFFu, aw, 16);

    if (half == 0) {
        float inv = (end > beg) ? (1.0f / (float)(end - beg)) : 0.0f;
        reinterpret_cast<float4*>(g_hn)[(size_t)warp * 16 + c] =
            make_float4(ax * inv, ay * inv, az * inv, aw * inv);
    }
}

// ---------------------------------------------------------------------------
// Layer-2 aggregation over pre-transformed z (32-dim): quarter-warp per
// edge (8 x float4 per 32-float row), four edges in flight, combine with
// shfl_xor(8) + shfl_xor(16).
// ---------------------------------------------------------------------------
__global__ void agg32_kernel(int nV) {
    int warp = (blockIdx.x * blockDim.x + threadIdx.x) >> 5;
    int lane = threadIdx.x & 31;
    if (warp >= nV) return;

    int beg = g_row[warp];
    int end = g_row[warp + 1];

    const float4* f4 = reinterpret_cast<const float4*>(g_z);
    int sub = lane >> 3;       // 0..3: edge slot
    int c   = lane & 7;        // float4 chunk within 32-float row

    float ax = 0.f, ay = 0.f, az = 0.f, aw = 0.f;
    for (int j = beg + sub; j < end; j += 4) {
        int s = g_adj[j];
        float4 v = __ldg(f4 + (size_t)s * 8 + c);
        ax += v.x; ay += v.y; az += v.z; aw += v.w;
    }
    #pragma unroll
    for (int m = 8; m <= 16; m <<= 1) {
        ax += __shfl_xor_sync(0xFFFFFFFFu, ax, m);
        ay += __shfl_xor_sync(0xFFFFFFFFu, ay, m);
        az += __shfl_xor_sync(0xFFFFFFFFu, az, m);
        aw += __shfl_xor_sync(0xFFFFFFFFu, aw, m);
    }
    if (lane < 8) {
        float inv = (end > beg) ? (1.0f / (float)(end - beg)) : 0.0f;
        reinterpret_cast<float4*>(g_hn2)[(size_t)warp * 8 + c] =
            make_float4(ax * inv, ay * inv, az * inv, aw * inv);
    }
}

// ---------------------------------------------------------------------------
// Node kernel, layer 1: h1 = relu( x @ Ws1 + g_hn @ Wn1 + b1 )
// 256 threads = 64 out-channels x 4 y-slots; FOUR nodes per thread per
// round (4 FMA per sW LDS -> FFMA-bound with smem slack). 16 nodes in
// flight, 64 nodes per block.
// ---------------------------------------------------------------------------
__global__ void node1_kernel(const float* __restrict__ x,
                             const float* __restrict__ Ws,
                             const float* __restrict__ Wn,
                             const float* __restrict__ b,
                             int nV) {
    __shared__ float sW[128 * 64];   // rows 0..63 = Ws, 64..127 = Wn
    __shared__ float sB[64];
    __shared__ float sIn[16][128];

    for (int i = threadIdx.x; i < 64 * 64; i += 256) {
        sW[i]           = Ws[i];
        sW[64 * 64 + i] = Wn[i];
    }
    if (threadIdx.x < 64) sB[threadIdx.x] = b[threadIdx.x];
    __syncthreads();

    int o = threadIdx.x & 63;
    int y = threadIdx.x >> 6;       // 0..3
    int base = blockIdx.x * 64;

    #pragma unroll 1
    for (int r = 0; r < 4; ++r) {   // 4 rounds x 16 nodes
        #pragma unroll
        for (int i = 0; i < 4; ++i) {
            int n = base + r * 16 + y + 4 * i;
            if (n < nV) {
                sIn[y + 4 * i][o]      = x   [(size_t)n * 64 + o];
                sIn[y + 4 * i][64 + o] = g_hn[(size_t)n * 64 + o];
            }
        }
        __syncthreads();
        float a0 = sB[o], a1 = a0, a2 = a0, a3 = a0;
        #pragma unroll
        for (int k = 0; k < 128; ++k) {
            float w = sW[k * 64 + o];
            a0 = fmaf(sIn[y][k],      w, a0);
            a1 = fmaf(sIn[y + 4][k],  w, a1);
            a2 = fmaf(sIn[y + 8][k],  w, a2);
            a3 = fmaf(sIn[y + 12][k], w, a3);
        }
        int n0 = base + r * 16 + y;
        if (n0 < nV)      g_h1[(size_t)n0 * 64 + o]        = fmaxf(a0, 0.0f);
        if (n0 + 4 < nV)  g_h1[(size_t)(n0 + 4) * 64 + o]  = fmaxf(a1, 0.0f);
        if (n0 + 8 < nV)  g_h1[(size_t)(n0 + 8) * 64 + o]  = fmaxf(a2, 0.0f);
        if (n0 + 12 < nV) g_h1[(size_t)(n0 + 12) * 64 + o] = fmaxf(a3, 0.0f);
        __syncthreads();
    }
}

// ---------------------------------------------------------------------------
// z-transform: z = h1 @ Wn2  (100k x 64 @ 64 x 32)
// 256 threads = 32 out x 8 y; two nodes per thread; 64 nodes per block.
// ---------------------------------------------------------------------------
__global__ void ztrans_kernel(const float* __restrict__ Wn, int nV) {
    __shared__ float sW[64 * 32];
    __shared__ float sIn[16][64];

    for (int i = threadIdx.x; i < 64 * 32; i += 256) sW[i] = Wn[i];
    __syncthreads();

    int o = threadIdx.x & 31;
    int y = threadIdx.x >> 5;       // 0..7
    int base = blockIdx.x * 64;

    #pragma unroll 1
    for (int r = 0; r < 4; ++r) {   // 4 rounds x 16 nodes
        int n0 = base + r * 16 + y;
        int n1 = n0 + 8;
        if (n0 < nV) {
            sIn[y][o]          = g_h1[(size_t)n0 * 64 + o];
            sIn[y][o + 32]     = g_h1[(size_t)n0 * 64 + o + 32];
        }
        if (n1 < nV) {
            sIn[y + 8][o]      = g_h1[(size_t)n1 * 64 + o];
            sIn[y + 8][o + 32] = g_h1[(size_t)n1 * 64 + o + 32];
        }
        __syncthreads();
        float a0 = 0.f, a1 = 0.f;
        #pragma unroll
        for (int k = 0; k < 64; ++k) {
            float w = sW[k * 32 + o];
            a0 = fmaf(sIn[y][k],     w, a0);
            a1 = fmaf(sIn[y + 8][k], w, a1);
        }
        if (n0 < nV) g_z[(size_t)n0 * 32 + o] = a0;
        if (n1 < nV) g_z[(size_t)n1 * 32 + o] = a1;
        __syncthreads();
    }
}

// ---------------------------------------------------------------------------
// Node kernel, layer 2: out = h1 @ Ws2 + g_hn2 + b2  (K=64 GEMM only)
// 256 threads = 32 out x 8 y; two nodes per thread; 64 nodes per block.
// ---------------------------------------------------------------------------
__global__ void node2_kernel(const float* __restrict__ Ws,
                             const float* __restrict__ b,
                             float* __restrict__ out,
                             int nV) {
    __shared__ float sW[64 * 32];
    __shared__ float sB[32];
    __shared__ float sIn[16][64];

    for (int i = threadIdx.x; i < 64 * 32; i += 256) sW[i] = Ws[i];
    if (threadIdx.x < 32) sB[threadIdx.x] = b[threadIdx.x];
    __syncthreads();

    int o = threadIdx.x & 31;
    int y = threadIdx.x >> 5;       // 0..7
    int base = blockIdx.x * 64;

    #pragma unroll 1
    for (int r = 0; r < 4; ++r) {
        int n0 = base + r * 16 + y;
        int n1 = n0 + 8;
        if (n0 < nV) {
            sIn[y][o]          = g_h1[(size_t)n0 * 64 + o];
            sIn[y][o + 32]     = g_h1[(size_t)n0 * 64 + o + 32];
        }
        if (n1 < nV) {
            sIn[y + 8][o]      = g_h1[(size_t)n1 * 64 + o];
            sIn[y + 8][o + 32] = g_h1[(size_t)n1 * 64 + o + 32];
        }
        __syncthreads();
        float a0 = sB[o], a1 = a0;
        #pragma unroll
        for (int k = 0; k < 64; ++k) {
            float w = sW[k * 32 + o];
            a0 = fmaf(sIn[y][k],     w, a0);
            a1 = fmaf(sIn[y + 8][k], w, a1);
        }
        if (n0 < nV) out[(size_t)n0 * 32 + o] = a0 + g_hn2[(size_t)n0 * 32 + o];
        if (n1 < nV) out[(size_t)n1 * 32 + o] = a1 + g_hn2[(size_t)n1 * 32 + o];
        __syncthreads();
    }
}

// ---------------------------------------------------------------------------
// Launch (kernel launches only — fully graph-capturable)
// ---------------------------------------------------------------------------
extern "C" void kernel_launch(void* const* d_in, const int* in_sizes, int n_in,
                              void* d_out, int out_size) {
    const float* x    = (const float*)d_in[0];
    const void*  src  = d_in[1];
    const void*  dst  = d_in[2];
    const float* Ws1  = (const float*)d_in[3];
    const float* Wn1  = (const float*)d_in[4];
    const float* b1   = (const float*)d_in[5];
    const float* Ws2  = (const float*)d_in[6];
    const float* Wn2  = (const float*)d_in[7];
    const float* b2   = (const float*)d_in[8];
    float*       out  = (float*)d_out;

    int nV = in_sizes[0] / 64;
    int nE = in_sizes[1];

    int eb = (nE + 255) / 256;
    int vb = (nV + 255) / 256;
    int sb = (nV + 1023) / 1024;     // <=128 scan blocks

    detect_kernel<<<1, 1>>>((const int*)dst);
    zero_counts<<<vb, 256>>>(nV);
    hist_kernel<<<eb, 256>>>(dst, nE, nV);
    scan_block<<<sb, 1024>>>(nV);
    scan_part<<<1, 128>>>(sb, nV);
    scan_add<<<sb, 1024>>>(nV);
    fill_kernel<<<eb, 256>>>(src, dst, nE, nV);

    int ab = (nV * 32 + 255) / 256;  // one warp per node
    int nb = (nV + 63) / 64;

    agg64_kernel<<<ab, 256>>>(x, nV);
    node1_kernel<<<nb, 256>>>(x, Ws1, Wn1, b1, nV);
    ztrans_kernel<<<nb, 256>>>(Wn2, nV);
    agg32_kernel<<<ab, 256>>>(nV);
    node2_kernel<<<nb, 256>>>(Ws2, b2, out, nV);
}